// round 14
// baseline (speedup 1.0000x reference)
#include <cuda_runtime.h>
#include <cuda_bf16.h>
#include <cstdint>

// Problem constants: B=4, S=2048, D=1024, H=16, HD=64
#define B_ 4
#define H_ 16
#define S_ 2048
#define D_ 1024
#define HD_ 64

// Scratch (allocation-free rule: __device__ globals).
__device__ float g_q[(size_t)B_ * H_ * S_ * HD_];   // [b,h,s,hd]
__device__ float g_k[(size_t)B_ * H_ * S_ * HD_];
__device__ float g_v[(size_t)B_ * H_ * S_ * HD_];
__device__ float g_ao[(size_t)B_ * S_ * D_];        // attention output [b*s, d]

// ============================================================================
// mma.sync m16n8k16 bf16 (baseline PTX; compiles for plain sm_103)
// bf16 2-split 3-product emulation: D += Ahi*Bhi + Ahi*Blo + Alo*Bhi.
// ============================================================================
#define MMA16816(d, a, b0, b1)                                               \
    asm volatile("mma.sync.aligned.m16n8k16.row.col.f32.bf16.bf16.f32 "      \
                 "{%0,%1,%2,%3}, {%4,%5,%6,%7}, {%8,%9}, {%0,%1,%2,%3};"     \
                 : "+f"((d)[0]), "+f"((d)[1]), "+f"((d)[2]), "+f"((d)[3])    \
                 : "r"((a)[0]), "r"((a)[1]), "r"((a)[2]), "r"((a)[3]),       \
                   "r"(b0), "r"(b1))

__device__ __forceinline__ void split2(float x0, float x1,
                                       uint32_t& hi, uint32_t& lo) {
    __nv_bfloat16 h0 = __float2bfloat16_rn(x0);
    __nv_bfloat16 h1 = __float2bfloat16_rn(x1);
    float r0 = x0 - __bfloat162float(h0);
    float r1 = x1 - __bfloat162float(h1);
    __nv_bfloat16 l0 = __float2bfloat16_rn(r0);
    __nv_bfloat16 l1 = __float2bfloat16_rn(r1);
    hi = (uint32_t)__bfloat16_as_ushort(h0) |
         ((uint32_t)__bfloat16_as_ushort(h1) << 16);
    lo = (uint32_t)__bfloat16_as_ushort(l0) |
         ((uint32_t)__bfloat16_as_ushort(l1) << 16);
}

// ============================================================================
// Emulated-bf16 MMA GEMM: BK=32, DOUBLE-BUFFERED, 2 CTAs/SM,
// conflict-free stride-20 smem, B XOR swizzle, ONE barrier per k-iter.
// Out[M=8192, N] = A[M,1024] @ W[1024,N] + bias, CTA 128x128.
// MODE 0: N=1024, A=g_ao, row-major Out. MODE 1: N=3072, scatter q/k/v.
// ============================================================================
#define KST 20
#define GT32 (128 * KST)                 // u32 per sub-array (2560)
#define GBUF (4 * GT32)                  // u32 per buffer (Ahi,Alo,Bhi,Blo)
#define GEMM_SMEM_BYTES (2 * GBUF * 4)   // 81920 (80KB/CTA, 2 CTAs = 160KB/SM)

template <int MODE, int NDIM>
__global__ void __launch_bounds__(256, 2) gemm_mma(
    const float* __restrict__ Ain,
    const float* __restrict__ W,
    const float* __restrict__ bias,
    float* __restrict__ Out)
{
    extern __shared__ uint32_t dsm[];

    const float* A = (MODE == 0) ? g_ao : Ain;

    const int tid = threadIdx.x;
    const int wid = tid >> 5;
    const int lane = tid & 31;
    const int g = lane >> 2;
    const int t = lane & 3;
    const int wm = wid & 3;
    const int wn = wid >> 2;
    const int bm = blockIdx.y * 128;
    const int bn = blockIdx.x * 128;

    // staging coords
    const int arow = tid >> 4;           // 0..15 (+16/iter, 8 iters)
    const int akp  = tid & 15;           // 0..15
    const int bn_l = tid & 127;
    const int bkp0 = tid >> 7;           // 0..1 (+2/iter, 8 iters)
    const int bswz = (bn_l >> 3) & 3;

    float acc[2][8][4];
#pragma unroll
    for (int i = 0; i < 2; i++)
#pragma unroll
        for (int j = 0; j < 8; j++)
#pragma unroll
            for (int c = 0; c < 4; c++) acc[i][j][c] = 0.0f;

    // ---- prologue: stage tile 0 into buffer 0 ----
    {
        uint32_t* pAh = dsm;
        uint32_t* pAl = pAh + GT32;
        uint32_t* pBh = pAl + GT32;
        uint32_t* pBl = pBh + GT32;
#pragma unroll
        for (int i = 0; i < 8; i++) {
            int row = arow + i * 16;
            float2 v = *(const float2*)&A[(size_t)(bm + row) * 1024 + akp * 2];
            split2(v.x, v.y, pAh[row * KST + akp], pAl[row * KST + akp]);
        }
#pragma unroll
        for (int i = 0; i < 8; i++) {
            int kp = bkp0 + i * 2;
            float w0 = W[(size_t)(kp * 2) * NDIM + bn + bn_l];
            float w1 = W[(size_t)(kp * 2 + 1) * NDIM + bn + bn_l];
            int kps = kp ^ bswz;
            split2(w0, w1, pBh[bn_l * KST + kps], pBl[bn_l * KST + kps]);
        }
    }
    __syncthreads();

    for (int kc = 0; kc < 32; kc++) {
        const int cur = kc & 1;
        const int nxt = cur ^ 1;
        const bool more = (kc + 1 < 32);

        // ---- stage NEXT tile into the other buffer (independent of MMAs;
        //      textually first so ptxas issues the LDGs early) ----
        if (more) {
            const int k1 = (kc + 1) * 32;
            uint32_t* pAh = dsm + nxt * GBUF;
            uint32_t* pAl = pAh + GT32;
            uint32_t* pBh = pAl + GT32;
            uint32_t* pBl = pBh + GT32;
#pragma unroll
            for (int i = 0; i < 8; i++) {
                int row = arow + i * 16;
                float2 v = *(const float2*)&A[(size_t)(bm + row) * 1024 + k1 + akp * 2];
                split2(v.x, v.y, pAh[row * KST + akp], pAl[row * KST + akp]);
            }
#pragma unroll
            for (int i = 0; i < 8; i++) {
                int kp = bkp0 + i * 2;
                float w0 = W[(size_t)(k1 + kp * 2) * NDIM + bn + bn_l];
                float w1 = W[(size_t)(k1 + kp * 2 + 1) * NDIM + bn + bn_l];
                int kps = kp ^ bswz;
                split2(w0, w1, pBh[bn_l * KST + kps], pBl[bn_l * KST + kps]);
            }
        }

        // ---- MMAs on current buffer: 2 k16-steps ----
        {
            const uint32_t* pAh = dsm + cur * GBUF;
            const uint32_t* pAl = pAh + GT32;
            const uint32_t* pBh = pAl + GT32;
            const uint32_t* pBl = pBh + GT32;
#pragma unroll
            for (int ks = 0; ks < 2; ks++) {
                const int kp0 = ks * 8;
                uint32_t ah[2][4], al[2][4];
#pragma unroll
                for (int mt = 0; mt < 2; mt++) {
                    int r0 = (wm * 32 + mt * 16 + g) * KST;
                    ah[mt][0] = pAh[r0 + kp0 + t];
                    ah[mt][1] = pAh[r0 + 8 * KST + kp0 + t];
                    ah[mt][2] = pAh[r0 + kp0 + t + 4];
                    ah[mt][3] = pAh[r0 + 8 * KST + kp0 + t + 4];
                    al[mt][0] = pAl[r0 + kp0 + t];
                    al[mt][1] = pAl[r0 + 8 * KST + kp0 + t];
                    al[mt][2] = pAl[r0 + kp0 + t + 4];
                    al[mt][3] = pAl[r0 + 8 * KST + kp0 + t + 4];
                }
#pragma unroll
                for (int nt = 0; nt < 8; nt++) {
                    const int s = nt & 3;
                    int nr = (wn * 64 + nt * 8 + g) * KST;
                    uint32_t bh0 = pBh[nr + ((kp0 + t) ^ s)];
                    uint32_t bh1 = pBh[nr + ((kp0 + t + 4) ^ s)];
                    uint32_t bl0 = pBl[nr + ((kp0 + t) ^ s)];
                    uint32_t bl1 = pBl[nr + ((kp0 + t + 4) ^ s)];
#pragma unroll
                    for (int mt = 0; mt < 2; mt++) {
                        MMA16816(acc[mt][nt], ah[mt], bh0, bh1);
                        MMA16816(acc[mt][nt], ah[mt], bl0, bl1);
                        MMA16816(acc[mt][nt], al[mt], bh0, bh1);
                    }
                }
            }
        }
        __syncthreads();   // next buffer complete; current free for overwrite
    }

    // ---- epilogue ----
#pragma unroll
    for (int mt = 0; mt < 2; mt++) {
        int row0 = bm + wm * 32 + mt * 16 + g;
#pragma unroll
        for (int nt = 0; nt < 8; nt++) {
            int col = bn + wn * 64 + nt * 8 + t * 2;
            float b0 = bias[col], b1 = bias[col + 1];
            float2 v0 = make_float2(acc[mt][nt][0] + b0, acc[mt][nt][1] + b1);
            float2 v1 = make_float2(acc[mt][nt][2] + b0, acc[mt][nt][3] + b1);
            if (MODE == 0) {
                *(float2*)&Out[(size_t)row0 * NDIM + col] = v0;
                *(float2*)&Out[(size_t)(row0 + 8) * NDIM + col] = v1;
            } else {
                int which = col >> 10;
                int h = (col & 1023) >> 6;
                int hd = col & 63;
                float* dst = (which == 0) ? g_q : (which == 1) ? g_k : g_v;
                int b = row0 >> 11, s = row0 & 2047;
                *(float2*)&dst[(((size_t)b * H_ + h) * S_ + s) * HD_ + hd] = v0;
                int r1 = row0 + 8;
                b = r1 >> 11; s = r1 & 2047;
                *(float2*)&dst[(((size_t)b * H_ + h) * S_ + s) * HD_ + hd] = v1;
            }
        }
    }
}

// ============================================================================
// Flash attention — R12 version exactly (measured 443us):
// BQ=256, 512 threads (16 warps), double-buffered K/V, no reg cap.
// ============================================================================
#define KPV 36
#define QT256 (256 * KPV)
#define KVTILE (64 * KPV)
#define KVBUF (4 * KVTILE)
#define FLASH_SMEM_BYTES ((2 * QT256 + 2 * KVBUF) * 4)   // 147456

__global__ void __launch_bounds__(512) flash_mma()
{
    extern __shared__ uint32_t su[];
    uint32_t* sQh = su;
    uint32_t* sQl = sQh + QT256;
    uint32_t* kvbase = sQl + QT256;

    const int z  = blockIdx.x;
    const int bh = z >> 3;
    const int qt = 7 - (z & 7);          // big tiles first
    const int b  = bh >> 4;
    const int h  = bh & 15;

    const int tid = threadIdx.x;
    const int wid = tid >> 5;            // 0..15
    const int lane = tid & 31;
    const int g = lane >> 2;
    const int t = lane & 3;

    const float NEG_INF = __int_as_float(0xff800000);

    const float* kbase = g_k + (size_t)bh * S_ * HD_;
    const float* vbase = g_v + (size_t)bh * S_ * HD_;

    // ---- stage Q (pre-scaled), single buffer: 256 rows x 32 kpairs ----
    {
        const float* qb = g_q + ((size_t)bh * S_ + qt * 256) * HD_;
#pragma unroll
        for (int i = 0; i < 16; i++) {
            int idx = tid + i * 512;
            int row = idx >> 5, kp = idx & 31;
            float2 v = *(const float2*)&qb[row * 64 + kp * 2];
            split2(v.x * 0.125f, v.y * 0.125f,
                   sQh[row * KPV + kp], sQl[row * KPV + kp]);
        }
    }

    float m0 = NEG_INF, m1 = NEG_INF, l0 = 0.0f, l1 = 0.0f;
    float acco[8][4];
#pragma unroll
    for (int nt = 0; nt < 8; nt++)
#pragma unroll
        for (int c = 0; c < 4; c++) acco[nt][c] = 0.0f;

    const int ktmax = 4 * qt + 3;
    const int rg0 = qt * 256 + wid * 16 + g;
    const int warp_row_hi = qt * 256 + wid * 16 + 15;

    // ---- prologue: stage K/V tile 0 into buffer 0 ----
    {
        uint32_t* pKh = kvbase;
        uint32_t* pKl = pKh + KVTILE;
        uint32_t* pVh = pKl + KVTILE;
        uint32_t* pVl = pVh + KVTILE;
#pragma unroll
        for (int i = 0; i < 4; i++) {
            int idx = tid + i * 512;
            int row = idx >> 5, kp = idx & 31;
            float2 v = *(const float2*)&kbase[(size_t)row * 64 + kp * 2];
            split2(v.x, v.y, pKh[row * KPV + kp], pKl[row * KPV + kp]);
        }
#pragma unroll
        for (int i = 0; i < 4; i++) {
            int idx = tid + i * 512;
            int hd = idx & 63, sp = idx >> 6;
            float v0 = vbase[(size_t)(sp * 2) * 64 + hd];
            float v1 = vbase[(size_t)(sp * 2 + 1) * 64 + hd];
            split2(v0, v1, pVh[hd * KPV + sp], pVl[hd * KPV + sp]);
        }
    }
    __syncthreads();

    float2 rk[4];
    float rv0[4], rv1[4];

    for (int kt = 0; kt <= ktmax; kt++) {
        const int cur = kt & 1;
        const int nxt = cur ^ 1;
        const bool more = (kt < ktmax);

        // ---- issue next K/V tile's global loads ----
        if (more) {
            const float* kbp = kbase + (size_t)(kt + 1) * 64 * HD_;
            const float* vbp = vbase + (size_t)(kt + 1) * 64 * HD_;
#pragma unroll
            for (int i = 0; i < 4; i++) {
                int idx = tid + i * 512;
                int row = idx >> 5, kp = idx & 31;
                rk[i] = *(const float2*)&kbp[(size_t)row * 64 + kp * 2];
            }
#pragma unroll
            for (int i = 0; i < 4; i++) {
                int idx = tid + i * 512;
                int hd = idx & 63, sp = idx >> 6;
                rv0[i] = vbp[(size_t)(sp * 2) * 64 + hd];
                rv1[i] = vbp[(size_t)(sp * 2 + 1) * 64 + hd];
            }
        }

        // ---- compute on current buffer (warps above causal line) ----
        if (warp_row_hi >= kt * 64) {
            const uint32_t* pKh = kvbase + cur * KVBUF;
            const uint32_t* pKl = pKh + KVTILE;
            const uint32_t* pVh = pKl + KVTILE;
            const uint32_t* pVl = pVh + KVTILE;

            // QK^T
            float accs[8][4];
#pragma unroll
            for (int nt = 0; nt < 8; nt++)
#pragma unroll
                for (int c = 0; c < 4; c++) accs[nt][c] = 0.0f;

#pragma unroll
            for (int ks = 0; ks < 4; ks++) {
                const int r0s = (wid * 16 + g) * KPV;
                const int kpb = ks * 8 + t;
                uint32_t ah[4] = { sQh[r0s + kpb],     sQh[r0s + 8 * KPV + kpb],
                                   sQh[r0s + kpb + 4], sQh[r0s + 8 * KPV + kpb + 4] };
                uint32_t al[4] = { sQl[r0s + kpb],     sQl[r0s + 8 * KPV + kpb],
                                   sQl[r0s + kpb + 4], sQl[r0s + 8 * KPV + kpb + 4] };
#pragma unroll
                for (int nt = 0; nt < 8; nt++) {
                    int nr = (nt * 8 + g) * KPV;
                    uint32_t bh0 = pKh[nr + kpb], bh1 = pKh[nr + kpb + 4];
                    uint32_t bl0 = pKl[nr + kpb], bl1 = pKl[nr + kpb + 4];
                    MMA16816(accs[nt], ah, bh0, bh1);
                    MMA16816(accs[nt], ah, bl0, bl1);
                    MMA16816(accs[nt], al, bh0, bh1);
                }
            }

            // causal mask
            if (kt >= 4 * qt) {
                const int rg1 = rg0 + 8;
#pragma unroll
                for (int nt = 0; nt < 8; nt++) {
                    int c0 = kt * 64 + nt * 8 + t * 2;
                    int c1 = c0 + 1;
                    if (c0 > rg0) accs[nt][0] = NEG_INF;
                    if (c1 > rg0) accs[nt][1] = NEG_INF;
                    if (c0 > rg1) accs[nt][2] = NEG_INF;
                    if (c1 > rg1) accs[nt][3] = NEG_INF;
                }
            }

            // warp-local online softmax
            float rm0 = NEG_INF, rm1 = NEG_INF;
#pragma unroll
            for (int nt = 0; nt < 8; nt++) {
                rm0 = fmaxf(rm0, fmaxf(accs[nt][0], accs[nt][1]));
                rm1 = fmaxf(rm1, fmaxf(accs[nt][2], accs[nt][3]));
            }
            rm0 = fmaxf(rm0, __shfl_xor_sync(0xFFFFFFFF, rm0, 1));
            rm0 = fmaxf(rm0, __shfl_xor_sync(0xFFFFFFFF, rm0, 2));
            rm1 = fmaxf(rm1, __shfl_xor_sync(0xFFFFFFFF, rm1, 1));
            rm1 = fmaxf(rm1, __shfl_xor_sync(0xFFFFFFFF, rm1, 2));

            float mn0 = fmaxf(m0, rm0), mn1 = fmaxf(m1, rm1);
            float a0 = __expf(m0 - mn0);
            float a1 = __expf(m1 - mn1);

            uint32_t pah[4][4], pal[4][4];
            float rs0 = 0.0f, rs1 = 0.0f;
#pragma unroll
            for (int nt = 0; nt < 8; nt++) {
                float p0 = __expf(accs[nt][0] - mn0);
                float p1 = __expf(accs[nt][1] - mn0);
                float p2 = __expf(accs[nt][2] - mn1);
                float p3 = __expf(accs[nt][3] - mn1);
                rs0 += p0 + p1;
                rs1 += p2 + p3;
                uint32_t h01, l01, h23, l23;
                split2(p0, p1, h01, l01);
                split2(p2, p3, h23, l23);
                int ks = nt >> 1, half = nt & 1;
                pah[ks][half * 2]     = h01;
                pah[ks][half * 2 + 1] = h23;
                pal[ks][half * 2]     = l01;
                pal[ks][half * 2 + 1] = l23;
            }
            rs0 += __shfl_xor_sync(0xFFFFFFFF, rs0, 1);
            rs0 += __shfl_xor_sync(0xFFFFFFFF, rs0, 2);
            rs1 += __shfl_xor_sync(0xFFFFFFFF, rs1, 1);
            rs1 += __shfl_xor_sync(0xFFFFFFFF, rs1, 2);

            l0 = l0 * a0 + rs0;
            l1 = l1 * a1 + rs1;
            m0 = mn0;
            m1 = mn1;

#pragma unroll
            for (int nt = 0; nt < 8; nt++) {
                acco[nt][0] *= a0; acco[nt][1] *= a0;
                acco[nt][2] *= a1; acco[nt][3] *= a1;
            }

            // PV
#pragma unroll
            for (int ks = 0; ks < 4; ks++) {
                const int kpb = ks * 8 + t;
#pragma unroll
                for (int nt = 0; nt < 8; nt++) {
                    int nr = (nt * 8 + g) * KPV;
                    uint32_t bh0 = pVh[nr + kpb], bh1 = pVh[nr + kpb + 4];
                    uint32_t bl0 = pVl[nr + kpb], bl1 = pVl[nr + kpb + 4];
                    MMA16816(acco[nt], pah[ks], bh0, bh1);
                    MMA16816(acco[nt], pal[ks], bh0, bh1);
                    MMA16816(acco[nt], pah[ks], bl0, bl1);
                }
            }
        }

        // ---- convert + store next K/V tile ----
        if (more) {
            uint32_t* pKh = kvbase + nxt * KVBUF;
            uint32_t* pKl = pKh + KVTILE;
            uint32_t* pVh = pKl + KVTILE;
            uint32_t* pVl = pVh + KVTILE;
#pragma unroll
            for (int i = 0; i < 4; i++) {
                int idx = tid + i * 512;
                int row = idx >> 5, kp = idx & 31;
                split2(rk[i].x, rk[i].y,
                       pKh[row * KPV + kp], pKl[row * KPV + kp]);
            }
#pragma unroll
            for (int i = 0; i < 4; i++) {
                int idx = tid + i * 512;
                int hd = idx & 63, sp = idx >> 6;
                split2(rv0[i], rv1[i],
                       pVh[hd * KPV + sp], pVl[hd * KPV + sp]);
            }
        }
        __syncthreads();
    }

    // ---- epilogue: O / l -> g_ao[b*s][h*64 + c] ----
    const float i0 = 1.0f / l0;
    const float i1 = 1.0f / l1;
    const int sq = qt * 256 + wid * 16 + g;
#pragma unroll
    for (int nt = 0; nt < 8; nt++) {
        int col = h * 64 + nt * 8 + t * 2;
        float2 v0 = make_float2(acco[nt][0] * i0, acco[nt][1] * i0);
        float2 v1 = make_float2(acco[nt][2] * i1, acco[nt][3] * i1);
        *(float2*)&g_ao[((size_t)b * S_ + sq) * D_ + col] = v0;
        *(float2*)&g_ao[((size_t)b * S_ + sq + 8) * D_ + col] = v1;
    }
}

// ============================================================================
// Launch
// ============================================================================
extern "C" void kernel_launch(void* const* d_in, const int* in_sizes, int n_in,
                              void* d_out, int out_size)
{
    const float *x = nullptr, *w_attn = nullptr, *b_attn = nullptr;
    const float *w_proj = nullptr, *b_proj = nullptr;
    for (int i = 0; i < n_in; i++) {
        switch (in_sizes[i]) {
            case 8388608: x      = (const float*)d_in[i]; break;
            case 3145728: w_attn = (const float*)d_in[i]; break;
            case 3072:    b_attn = (const float*)d_in[i]; break;
            case 1048576: w_proj = (const float*)d_in[i]; break;
            case 1024:    b_proj = (const float*)d_in[i]; break;
            default: break;  // mask (ignored; causal handled analytically)
        }
    }
    if (!x)      x      = (const float*)d_in[0];
    if (!w_attn) w_attn = (const float*)d_in[2];
    if (!b_attn) b_attn = (const float*)d_in[3];
    if (!w_proj) w_proj = (const float*)d_in[4];
    if (!b_proj) b_proj = (const float*)d_in[5];

    const int M = B_ * S_;  // 8192

    cudaFuncSetAttribute(gemm_mma<1, 3072>,
                         cudaFuncAttributeMaxDynamicSharedMemorySize,
                         GEMM_SMEM_BYTES);
    cudaFuncSetAttribute(gemm_mma<0, 1024>,
                         cudaFuncAttributeMaxDynamicSharedMemorySize,
                         GEMM_SMEM_BYTES);
    cudaFuncSetAttribute(flash_mma,
                         cudaFuncAttributeMaxDynamicSharedMemorySize,
                         FLASH_SMEM_BYTES);

    // 1) QKV projection (dbuf + 2CTA + conflict-free), scatter to [b,h,s,hd]
    gemm_mma<1, 3072><<<dim3(3 * D_ / 128, M / 128), 256, GEMM_SMEM_BYTES>>>(
        x, w_attn, b_attn, nullptr);

    // 2) Fused causal flash attention (R12 measured-best: BQ=256, 512 thr)
    flash_mma<<<B_ * H_ * (S_ / 256), 512, FLASH_SMEM_BYTES>>>();

    // 3) Output projection -> d_out
    gemm_mma<0, 1024><<<dim3(D_ / 128, M / 128), 256, GEMM_SMEM_BYTES>>>(
        nullptr, w_proj, b_proj, (float*)d_out);
}

// round 15
// speedup vs baseline: 1.3365x; 1.3365x over previous
#include <cuda_runtime.h>
#include <cuda_fp16.h>
#include <cstdint>

// Problem constants: B=4, S=2048, D=1024, H=16, HD=64
#define B_ 4
#define H_ 16
#define S_ 2048
#define D_ 1024
#define HD_ 64

// Scratch (allocation-free rule: __device__ globals).
__device__ float g_q[(size_t)B_ * H_ * S_ * HD_];   // [b,h,s,hd]
__device__ float g_k[(size_t)B_ * H_ * S_ * HD_];
__device__ float g_v[(size_t)B_ * H_ * S_ * HD_];
__device__ float g_ao[(size_t)B_ * S_ * D_];        // attention output [b*s, d]

// ============================================================================
// mma.sync m16n8k16 fp16 (baseline PTX; compiles for plain sm_103)
// fp16 A-split 2-product emulation: D += Ahi*B + Alo*B.
// B rounded to fp16 (error ~2^-12, well under the 1e-3 threshold).
// ============================================================================
#define MMA16816(d, a, b0, b1)                                               \
    asm volatile("mma.sync.aligned.m16n8k16.row.col.f32.f16.f16.f32 "       \
                 "{%0,%1,%2,%3}, {%4,%5,%6,%7}, {%8,%9}, {%0,%1,%2,%3};"     \
                 : "+f"((d)[0]), "+f"((d)[1]), "+f"((d)[2]), "+f"((d)[3])    \
                 : "r"((a)[0]), "r"((a)[1]), "r"((a)[2]), "r"((a)[3]),       \
                   "r"(b0), "r"(b1))

__device__ __forceinline__ uint32_t packh(__half a, __half b) {
    return (uint32_t)__half_as_ushort(a) | ((uint32_t)__half_as_ushort(b) << 16);
}
__device__ __forceinline__ void split2h(float x0, float x1,
                                        uint32_t& hi, uint32_t& lo) {
    __half h0 = __float2half_rn(x0);
    __half h1 = __float2half_rn(x1);
    float r0 = x0 - __half2float(h0);
    float r1 = x1 - __half2float(h1);
    hi = packh(h0, h1);
    lo = packh(__float2half_rn(r0), __float2half_rn(r1));
}
__device__ __forceinline__ uint32_t cvt2h(float x0, float x1) {
    return packh(__float2half_rn(x0), __float2half_rn(x1));
}

// ============================================================================
// fp16 2-product MMA GEMM (R11 structure: single-buffered BK=64, 2 CTAs/SM,
// stride-36 conflict-free smem, B XOR swizzle). 3 smem arrays (Ahi,Alo,B).
// Out[M=8192, N] = A[M,1024] @ W[1024,N] + bias, CTA 128x128.
// MODE 0: N=1024, A=g_ao, row-major Out. MODE 1: N=3072, scatter q/k/v.
// ============================================================================
#define KST 36
#define GT64 (128 * KST)                 // u32 per sub-array (4608)
#define GEMM_SMEM_BYTES (3 * GT64 * 4)   // 55296 (54KB/CTA, 2 CTAs = 108KB/SM)

template <int MODE, int NDIM>
__global__ void __launch_bounds__(256, 2) gemm_mma(
    const float* __restrict__ Ain,
    const float* __restrict__ W,
    const float* __restrict__ bias,
    float* __restrict__ Out)
{
    extern __shared__ uint32_t dsm[];
    uint32_t* pAh = dsm;
    uint32_t* pAl = pAh + GT64;
    uint32_t* pB  = pAl + GT64;

    const float* A = (MODE == 0) ? g_ao : Ain;

    const int tid = threadIdx.x;
    const int wid = tid >> 5;
    const int lane = tid & 31;
    const int g = lane >> 2;
    const int t = lane & 3;
    const int wm = wid & 3;
    const int wn = wid >> 2;
    const int bm = blockIdx.y * 128;
    const int bn = blockIdx.x * 128;

    const int arow = tid >> 5;
    const int akp  = tid & 31;
    const int bn_l = tid & 127;
    const int bkp0 = tid >> 7;
    const int bswz = (bn_l >> 3) & 3;

    float acc[2][8][4];
#pragma unroll
    for (int i = 0; i < 2; i++)
#pragma unroll
        for (int j = 0; j < 8; j++)
#pragma unroll
            for (int c = 0; c < 4; c++) acc[i][j][c] = 0.0f;

    for (int kc = 0; kc < 16; kc++) {
        const int k0 = kc * 64;
        // ---- stage A: 128 rows x 32 kpairs; one warp per row; hi/lo split
#pragma unroll
        for (int i = 0; i < 16; i++) {
            int row = arow + i * 8;
            float2 v = *(const float2*)&A[(size_t)(bm + row) * 1024 + k0 + akp * 2];
            split2h(v.x, v.y, pAh[row * KST + akp], pAl[row * KST + akp]);
        }
        // ---- stage B: transpose w[k][n] -> smem[n][kp^s]; single fp16 ----
#pragma unroll
        for (int i = 0; i < 16; i++) {
            int kp = bkp0 + i * 2;
            float w0 = W[(size_t)(k0 + kp * 2) * NDIM + bn + bn_l];
            float w1 = W[(size_t)(k0 + kp * 2 + 1) * NDIM + bn + bn_l];
            pB[bn_l * KST + (kp ^ bswz)] = cvt2h(w0, w1);
        }
        __syncthreads();

        // ---- MMAs: 4 k16-steps, 2 products ----
#pragma unroll
        for (int ks = 0; ks < 4; ks++) {
            const int kp0 = ks * 8;
            uint32_t ah[2][4], al[2][4];
#pragma unroll
            for (int mt = 0; mt < 2; mt++) {
                int r0 = (wm * 32 + mt * 16 + g) * KST;
                ah[mt][0] = pAh[r0 + kp0 + t];
                ah[mt][1] = pAh[r0 + 8 * KST + kp0 + t];
                ah[mt][2] = pAh[r0 + kp0 + t + 4];
                ah[mt][3] = pAh[r0 + 8 * KST + kp0 + t + 4];
                al[mt][0] = pAl[r0 + kp0 + t];
                al[mt][1] = pAl[r0 + 8 * KST + kp0 + t];
                al[mt][2] = pAl[r0 + kp0 + t + 4];
                al[mt][3] = pAl[r0 + 8 * KST + kp0 + t + 4];
            }
#pragma unroll
            for (int nt = 0; nt < 8; nt++) {
                const int s = nt & 3;
                int nr = (wn * 64 + nt * 8 + g) * KST;
                uint32_t b0 = pB[nr + ((kp0 + t) ^ s)];
                uint32_t b1 = pB[nr + ((kp0 + t + 4) ^ s)];
#pragma unroll
                for (int mt = 0; mt < 2; mt++) {
                    MMA16816(acc[mt][nt], ah[mt], b0, b1);
                    MMA16816(acc[mt][nt], al[mt], b0, b1);
                }
            }
        }
        __syncthreads();
    }

    // ---- epilogue ----
#pragma unroll
    for (int mt = 0; mt < 2; mt++) {
        int row0 = bm + wm * 32 + mt * 16 + g;
#pragma unroll
        for (int nt = 0; nt < 8; nt++) {
            int col = bn + wn * 64 + nt * 8 + t * 2;
            float b0 = bias[col], b1 = bias[col + 1];
            float2 v0 = make_float2(acc[mt][nt][0] + b0, acc[mt][nt][1] + b1);
            float2 v1 = make_float2(acc[mt][nt][2] + b0, acc[mt][nt][3] + b1);
            if (MODE == 0) {
                *(float2*)&Out[(size_t)row0 * NDIM + col] = v0;
                *(float2*)&Out[(size_t)(row0 + 8) * NDIM + col] = v1;
            } else {
                int which = col >> 10;
                int h = (col & 1023) >> 6;
                int hd = col & 63;
                float* dst = (which == 0) ? g_q : (which == 1) ? g_k : g_v;
                int b = row0 >> 11, s = row0 & 2047;
                *(float2*)&dst[(((size_t)b * H_ + h) * S_ + s) * HD_ + hd] = v0;
                int r1 = row0 + 8;
                b = r1 >> 11; s = r1 & 2047;
                *(float2*)&dst[(((size_t)b * H_ + h) * S_ + s) * HD_ + hd] = v1;
            }
        }
    }
}

// ============================================================================
// Flash attention (R12 structure: BQ=256, 512 threads, double-buffered K/V),
// fp16 2-product: Q split hi/lo, K single; P split hi/lo, V single.
// ============================================================================
#define KPV 36
#define QT256 (256 * KPV)                // u32 per Q sub-array (9216)
#define KVTILE (64 * KPV)                // u32 per K or V array (2304)
#define KVBUF (2 * KVTILE)               // K,V single-precision-fp16 per buffer
#define FLASH_SMEM_BYTES ((2 * QT256 + 2 * KVBUF) * 4)   // 110592

__global__ void __launch_bounds__(512) flash_mma()
{
    extern __shared__ uint32_t su[];
    uint32_t* sQh = su;
    uint32_t* sQl = sQh + QT256;
    uint32_t* kvbase = sQl + QT256;

    const int z  = blockIdx.x;
    const int bh = z >> 3;
    const int qt = 7 - (z & 7);          // big tiles first
    const int b  = bh >> 4;
    const int h  = bh & 15;

    const int tid = threadIdx.x;
    const int wid = tid >> 5;            // 0..15
    const int lane = tid & 31;
    const int g = lane >> 2;
    const int t = lane & 3;

    const float NEG_INF = __int_as_float(0xff800000);

    const float* kbase = g_k + (size_t)bh * S_ * HD_;
    const float* vbase = g_v + (size_t)bh * S_ * HD_;

    // ---- stage Q (pre-scaled), hi/lo split, single buffer ----
    {
        const float* qb = g_q + ((size_t)bh * S_ + qt * 256) * HD_;
#pragma unroll
        for (int i = 0; i < 16; i++) {
            int idx = tid + i * 512;
            int row = idx >> 5, kp = idx & 31;
            float2 v = *(const float2*)&qb[row * 64 + kp * 2];
            split2h(v.x * 0.125f, v.y * 0.125f,
                    sQh[row * KPV + kp], sQl[row * KPV + kp]);
        }
    }

    float m0 = NEG_INF, m1 = NEG_INF, l0 = 0.0f, l1 = 0.0f;
    float acco[8][4];
#pragma unroll
    for (int nt = 0; nt < 8; nt++)
#pragma unroll
        for (int c = 0; c < 4; c++) acco[nt][c] = 0.0f;

    const int ktmax = 4 * qt + 3;
    const int rg0 = qt * 256 + wid * 16 + g;
    const int warp_row_hi = qt * 256 + wid * 16 + 15;

    // ---- prologue: stage K/V tile 0 into buffer 0 (single fp16) ----
    {
        uint32_t* pK = kvbase;
        uint32_t* pV = pK + KVTILE;
#pragma unroll
        for (int i = 0; i < 4; i++) {
            int idx = tid + i * 512;
            int row = idx >> 5, kp = idx & 31;
            float2 v = *(const float2*)&kbase[(size_t)row * 64 + kp * 2];
            pK[row * KPV + kp] = cvt2h(v.x, v.y);
        }
#pragma unroll
        for (int i = 0; i < 4; i++) {
            int idx = tid + i * 512;
            int hd = idx & 63, sp = idx >> 6;
            float v0 = vbase[(size_t)(sp * 2) * 64 + hd];
            float v1 = vbase[(size_t)(sp * 2 + 1) * 64 + hd];
            pV[hd * KPV + sp] = cvt2h(v0, v1);
        }
    }
    __syncthreads();

    float2 rk[4];
    float rv0[4], rv1[4];

    for (int kt = 0; kt <= ktmax; kt++) {
        const int cur = kt & 1;
        const int nxt = cur ^ 1;
        const bool more = (kt < ktmax);

        // ---- issue next K/V tile's global loads ----
        if (more) {
            const float* kbp = kbase + (size_t)(kt + 1) * 64 * HD_;
            const float* vbp = vbase + (size_t)(kt + 1) * 64 * HD_;
#pragma unroll
            for (int i = 0; i < 4; i++) {
                int idx = tid + i * 512;
                int row = idx >> 5, kp = idx & 31;
                rk[i] = *(const float2*)&kbp[(size_t)row * 64 + kp * 2];
            }
#pragma unroll
            for (int i = 0; i < 4; i++) {
                int idx = tid + i * 512;
                int hd = idx & 63, sp = idx >> 6;
                rv0[i] = vbp[(size_t)(sp * 2) * 64 + hd];
                rv1[i] = vbp[(size_t)(sp * 2 + 1) * 64 + hd];
            }
        }

        // ---- compute on current buffer (warps above causal line) ----
        if (warp_row_hi >= kt * 64) {
            const uint32_t* pK = kvbase + cur * KVBUF;
            const uint32_t* pV = pK + KVTILE;

            // QK^T (2 products: Qhi*K + Qlo*K)
            float accs[8][4];
#pragma unroll
            for (int nt = 0; nt < 8; nt++)
#pragma unroll
                for (int c = 0; c < 4; c++) accs[nt][c] = 0.0f;

#pragma unroll
            for (int ks = 0; ks < 4; ks++) {
                const int r0s = (wid * 16 + g) * KPV;
                const int kpb = ks * 8 + t;
                uint32_t ah[4] = { sQh[r0s + kpb],     sQh[r0s + 8 * KPV + kpb],
                                   sQh[r0s + kpb + 4], sQh[r0s + 8 * KPV + kpb + 4] };
                uint32_t al[4] = { sQl[r0s + kpb],     sQl[r0s + 8 * KPV + kpb],
                                   sQl[r0s + kpb + 4], sQl[r0s + 8 * KPV + kpb + 4] };
#pragma unroll
                for (int nt = 0; nt < 8; nt++) {
                    int nr = (nt * 8 + g) * KPV;
                    uint32_t b0 = pK[nr + kpb], b1 = pK[nr + kpb + 4];
                    MMA16816(accs[nt], ah, b0, b1);
                    MMA16816(accs[nt], al, b0, b1);
                }
            }

            // causal mask
            if (kt >= 4 * qt) {
                const int rg1 = rg0 + 8;
#pragma unroll
                for (int nt = 0; nt < 8; nt++) {
                    int c0 = kt * 64 + nt * 8 + t * 2;
                    int c1 = c0 + 1;
                    if (c0 > rg0) accs[nt][0] = NEG_INF;
                    if (c1 > rg0) accs[nt][1] = NEG_INF;
                    if (c0 > rg1) accs[nt][2] = NEG_INF;
                    if (c1 > rg1) accs[nt][3] = NEG_INF;
                }
            }

            // warp-local online softmax
            float rm0 = NEG_INF, rm1 = NEG_INF;
#pragma unroll
            for (int nt = 0; nt < 8; nt++) {
                rm0 = fmaxf(rm0, fmaxf(accs[nt][0], accs[nt][1]));
                rm1 = fmaxf(rm1, fmaxf(accs[nt][2], accs[nt][3]));
            }
            rm0 = fmaxf(rm0, __shfl_xor_sync(0xFFFFFFFF, rm0, 1));
            rm0 = fmaxf(rm0, __shfl_xor_sync(0xFFFFFFFF, rm0, 2));
            rm1 = fmaxf(rm1, __shfl_xor_sync(0xFFFFFFFF, rm1, 1));
            rm1 = fmaxf(rm1, __shfl_xor_sync(0xFFFFFFFF, rm1, 2));

            float mn0 = fmaxf(m0, rm0), mn1 = fmaxf(m1, rm1);
            float a0 = __expf(m0 - mn0);
            float a1 = __expf(m1 - mn1);

            // exp + P fragment packing (hi/lo split for 2-product PV)
            uint32_t pah[4][4], pal[4][4];
            float rs0 = 0.0f, rs1 = 0.0f;
#pragma unroll
            for (int nt = 0; nt < 8; nt++) {
                float p0 = __expf(accs[nt][0] - mn0);
                float p1 = __expf(accs[nt][1] - mn0);
                float p2 = __expf(accs[nt][2] - mn1);
                float p3 = __expf(accs[nt][3] - mn1);
                rs0 += p0 + p1;
                rs1 += p2 + p3;
                uint32_t h01, l01, h23, l23;
                split2h(p0, p1, h01, l01);
                split2h(p2, p3, h23, l23);
                int ks = nt >> 1, half = nt & 1;
                pah[ks][half * 2]     = h01;
                pah[ks][half * 2 + 1] = h23;
                pal[ks][half * 2]     = l01;
                pal[ks][half * 2 + 1] = l23;
            }
            rs0 += __shfl_xor_sync(0xFFFFFFFF, rs0, 1);
            rs0 += __shfl_xor_sync(0xFFFFFFFF, rs0, 2);
            rs1 += __shfl_xor_sync(0xFFFFFFFF, rs1, 1);
            rs1 += __shfl_xor_sync(0xFFFFFFFF, rs1, 2);

            l0 = l0 * a0 + rs0;
            l1 = l1 * a1 + rs1;
            m0 = mn0;
            m1 = mn1;

#pragma unroll
            for (int nt = 0; nt < 8; nt++) {
                acco[nt][0] *= a0; acco[nt][1] *= a0;
                acco[nt][2] *= a1; acco[nt][3] *= a1;
            }

            // PV (2 products: Phi*V + Plo*V)
#pragma unroll
            for (int ks = 0; ks < 4; ks++) {
                const int kpb = ks * 8 + t;
#pragma unroll
                for (int nt = 0; nt < 8; nt++) {
                    int nr = (nt * 8 + g) * KPV;
                    uint32_t b0 = pV[nr + kpb], b1 = pV[nr + kpb + 4];
                    MMA16816(acco[nt], pah[ks], b0, b1);
                    MMA16816(acco[nt], pal[ks], b0, b1);
                }
            }
        }

        // ---- convert + store next K/V tile ----
        if (more) {
            uint32_t* pK = kvbase + nxt * KVBUF;
            uint32_t* pV = pK + KVTILE;
#pragma unroll
            for (int i = 0; i < 4; i++) {
                int idx = tid + i * 512;
                int row = idx >> 5, kp = idx & 31;
                pK[row * KPV + kp] = cvt2h(rk[i].x, rk[i].y);
            }
#pragma unroll
            for (int i = 0; i < 4; i++) {
                int idx = tid + i * 512;
                int hd = idx & 63, sp = idx >> 6;
                pV[hd * KPV + sp] = cvt2h(rv0[i], rv1[i]);
            }
        }
        __syncthreads();
    }

    // ---- epilogue: O / l -> g_ao[b*s][h*64 + c] ----
    const float i0 = 1.0f / l0;
    const float i1 = 1.0f / l1;
    const int sq = qt * 256 + wid * 16 + g;
#pragma unroll
    for (int nt = 0; nt < 8; nt++) {
        int col = h * 64 + nt * 8 + t * 2;
        float2 v0 = make_float2(acco[nt][0] * i0, acco[nt][1] * i0);
        float2 v1 = make_float2(acco[nt][2] * i1, acco[nt][3] * i1);
        *(float2*)&g_ao[((size_t)b * S_ + sq) * D_ + col] = v0;
        *(float2*)&g_ao[((size_t)b * S_ + sq + 8) * D_ + col] = v1;
    }
}

// ============================================================================
// Launch
// ============================================================================
extern "C" void kernel_launch(void* const* d_in, const int* in_sizes, int n_in,
                              void* d_out, int out_size)
{
    const float *x = nullptr, *w_attn = nullptr, *b_attn = nullptr;
    const float *w_proj = nullptr, *b_proj = nullptr;
    for (int i = 0; i < n_in; i++) {
        switch (in_sizes[i]) {
            case 8388608: x      = (const float*)d_in[i]; break;
            case 3145728: w_attn = (const float*)d_in[i]; break;
            case 3072:    b_attn = (const float*)d_in[i]; break;
            case 1048576: w_proj = (const float*)d_in[i]; break;
            case 1024:    b_proj = (const float*)d_in[i]; break;
            default: break;  // mask (ignored; causal handled analytically)
        }
    }
    if (!x)      x      = (const float*)d_in[0];
    if (!w_attn) w_attn = (const float*)d_in[2];
    if (!b_attn) b_attn = (const float*)d_in[3];
    if (!w_proj) w_proj = (const float*)d_in[4];
    if (!b_proj) b_proj = (const float*)d_in[5];

    const int M = B_ * S_;  // 8192

    cudaFuncSetAttribute(gemm_mma<1, 3072>,
                         cudaFuncAttributeMaxDynamicSharedMemorySize,
                         GEMM_SMEM_BYTES);
    cudaFuncSetAttribute(gemm_mma<0, 1024>,
                         cudaFuncAttributeMaxDynamicSharedMemorySize,
                         GEMM_SMEM_BYTES);
    cudaFuncSetAttribute(flash_mma,
                         cudaFuncAttributeMaxDynamicSharedMemorySize,
                         FLASH_SMEM_BYTES);

    // 1) QKV projection (fp16 2-product), scatter to [b,h,s,hd]
    gemm_mma<1, 3072><<<dim3(3 * D_ / 128, M / 128), 256, GEMM_SMEM_BYTES>>>(
        x, w_attn, b_attn, nullptr);

    // 2) Fused causal flash attention (fp16 2-product)
    flash_mma<<<B_ * H_ * (S_ / 256), 512, FLASH_SMEM_BYTES>>>();

    // 3) Output projection (fp16 2-product) -> d_out
    gemm_mma<0, 1024><<<dim3(D_ / 128, M / 128), 256, GEMM_SMEM_BYTES>>>(
        nullptr, w_proj, b_proj, (float*)d_out);
}